// round 8
// baseline (speedup 1.0000x reference)
#include <cuda_runtime.h>

#define BATCH 32
#define NCH   4
#define HH    512
#define WW    512
#define PLANE (HH*WW)          /* 262144 */
#define NSTEPS 8
#define D_SCALE 0.2f
#define RHO_SCALE 0.1f

#define TILE   16               /* output rows per block (fused kernel) */
#define INR    (TILE + 4)       /* 20 input rows incl. 2-step halo */
#define MIDR   (TILE + 2)       /* 18 intermediate rows */
#define THREADS_F 512
#define SMEMF  ((INR + MIDR) * WW * 4)   /* 77824 bytes */

// Ping-pong scratch for the evolving channel-0 field (2 x 32 MiB).
__device__ float g_buf0[BATCH * PLANE];
__device__ float g_buf1[BATCH * PLANE];
// Sums at even steps 0,2,4,6,8: slot k = state entering fused kernel k.
__device__ float g_sum0[5 * BATCH];
__device__ float g_sumsq[5 * BATCH];
// Constant sums of channels 1..3 (index (c-1)*BATCH + b).
__device__ float g_sumc[3 * BATCH];

__global__ void zero_sums_kernel() {
    int i = threadIdx.x;
    if (i < 5 * BATCH) { g_sum0[i] = 0.0f; g_sumsq[i] = 0.0f; }
    if (i < 3 * BATCH) g_sumc[i] = 0.0f;
}

// Copy channels 1..3 input->output; reduce sums (and sumsq for ch0).
// grid = (PLANE/4/256, BATCH*NCH), block = 256.
__global__ void init_kernel(const float* __restrict__ x, float* __restrict__ out) {
    const int p = blockIdx.y;            // plane id = b*4 + c
    const int b = p >> 2;
    const int c = p & 3;
    const int i = blockIdx.x * blockDim.x + threadIdx.x;

    const float4* src = (const float4*)(x + (size_t)p * PLANE);
    float4 v = src[i];
    if (c != 0) {
        ((float4*)(out + (size_t)p * PLANE))[i] = v;
    }
    float s  = (v.x + v.y) + (v.z + v.w);
    float s2 = (v.x * v.x + v.y * v.y) + (v.z * v.z + v.w * v.w);

    #pragma unroll
    for (int o = 16; o > 0; o >>= 1) {
        s  += __shfl_down_sync(0xffffffffu, s,  o);
        s2 += __shfl_down_sync(0xffffffffu, s2, o);
    }
    __shared__ float ws[8], ws2[8];
    const int lane = threadIdx.x & 31;
    const int w    = threadIdx.x >> 5;
    if (lane == 0) { ws[w] = s; ws2[w] = s2; }
    __syncthreads();
    if (w == 0) {
        s  = (lane < 8) ? ws[lane]  : 0.0f;
        s2 = (lane < 8) ? ws2[lane] : 0.0f;
        #pragma unroll
        for (int o = 4; o > 0; o >>= 1) {
            s  += __shfl_down_sync(0x000000ffu, s,  o);
            s2 += __shfl_down_sync(0x000000ffu, s2, o);
        }
        if (lane == 0) {
            if (c == 0) {
                atomicAdd(&g_sum0[b],  s);
                atomicAdd(&g_sumsq[b], s2);
            } else {
                atomicAdd(&g_sumc[(c - 1) * BATCH + b], s);
            }
        }
    }
}

// TWO fused reaction-diffusion steps (s, s+1) on channel 0.
// D1/rho1 for the second sub-step come from the analytically propagated sum:
//   sum_{s+1} = sum_s + rho_s * (sum_s - sumsq_s)   (periodic BC: sum(lap)=0)
// Tile: TILE output rows x 512; stages: gmem->smem (20 rows), step1->smem
// (18 rows), step2->gmem (16 rows) + reduce sum/sumsq of the final field.
// grid = (HH/TILE, BATCH) = (32, 32), block = 512, dyn smem = SMEMF.
__global__ __launch_bounds__(THREADS_F) void fused2_kernel(
        const float* __restrict__ src, int src_bstride,
        float* __restrict__ dst, int dst_bstride,
        const float* __restrict__ Wm,
        const float* __restrict__ bias,
        const int* __restrict__ t, int s) {
    extern __shared__ float sm[];
    float* smin = sm;                 // INR  rows x 512
    float* smid = sm + INR * WW;      // MIDR rows x 512

    const int b   = blockIdx.y;
    const int y0  = blockIdx.x * TILE;
    const int tid = threadIdx.x;

    const float* __restrict__ u = src + (size_t)b * src_bstride;
    float* __restrict__ v       = dst + (size_t)b * dst_bstride;

    // ---- Stage A: load 20 rows (y0-2 .. y0+17, periodic) into smem ----
    #pragma unroll
    for (int i = tid; i < INR * 128; i += THREADS_F) {
        const int r = i >> 7;
        const int c = (i & 127) << 2;
        const int gy = (y0 - 2 + r) & (HH - 1);
        *(float4*)(smin + r * WW + c) = *(const float4*)(u + (gy << 9) + c);
    }

    // ---- D/rho for both sub-steps (overlaps stage-A loads) ----
    const int slot = s >> 1;
    const float inv = 1.0f / (float)PLANE;
    const float sum_s = g_sum0[slot * BATCH + b];
    const float ssq_s = g_sumsq[slot * BATCH + b];
    const float f1 = g_sumc[0 * BATCH + b] * inv;
    const float f2 = g_sumc[1 * BATCH + b] * inv;
    const float f3 = g_sumc[2 * BATCH + b] * inv;
    const float zc0 = f1 * Wm[2] + f2 * Wm[4] + f3 * Wm[6] + bias[0];
    const float zc1 = f1 * Wm[3] + f2 * Wm[5] + f3 * Wm[7] + bias[1];
    const int tb = t[b];

    const float f0 = sum_s * inv;
    float D0 = D_SCALE   / (1.0f + expf(-(f0 * Wm[0] + zc0)));
    float r0 = RHO_SCALE / (1.0f + expf(-(f0 * Wm[1] + zc1)));
    if (tb <= s) { D0 = 0.0f; r0 = 0.0f; }

    const float sum_n = sum_s + r0 * (sum_s - ssq_s);   // exact under periodic BC
    const float f0n = sum_n * inv;
    float D1 = D_SCALE   / (1.0f + expf(-(f0n * Wm[0] + zc0)));
    float r1 = RHO_SCALE / (1.0f + expf(-(f0n * Wm[1] + zc1)));
    if (tb <= s + 1) { D1 = 0.0f; r1 = 0.0f; }

    __syncthreads();

    // ---- Stage B: first sub-step -> 18 intermediate rows in smem ----
    for (int i = tid; i < MIDR * 128; i += THREADS_F) {
        const int m = i >> 7;
        const int c = (i & 127) << 2;
        const float* rc = smin + (m + 1) * WW;
        const float4 C = *(const float4*)(rc + c);
        const float4 U = *(const float4*)(smin + m * WW + c);
        const float4 N = *(const float4*)(smin + (m + 2) * WW + c);
        const float le = rc[(c + WW - 1) & (WW - 1)];
        const float ri = rc[(c + 4) & (WW - 1)];
        float4 o;
        o.x = fmaf(D0, U.x + N.x + le  + C.y - 4.0f * C.x, fmaf(r0 * C.x, 1.0f - C.x, C.x));
        o.y = fmaf(D0, U.y + N.y + C.x + C.z - 4.0f * C.y, fmaf(r0 * C.y, 1.0f - C.y, C.y));
        o.z = fmaf(D0, U.z + N.z + C.y + C.w - 4.0f * C.z, fmaf(r0 * C.z, 1.0f - C.z, C.z));
        o.w = fmaf(D0, U.w + N.w + C.z + ri  - 4.0f * C.w, fmaf(r0 * C.w, 1.0f - C.w, C.w));
        *(float4*)(smid + m * WW + c) = o;
    }
    __syncthreads();

    // ---- Stage C: second sub-step -> gmem + reduce sum/sumsq of new field ----
    float acc = 0.0f, acc2 = 0.0f;
    #pragma unroll
    for (int i = tid; i < TILE * 128; i += THREADS_F) {
        const int r = i >> 7;
        const int c = (i & 127) << 2;
        const float* rc = smid + (r + 1) * WW;
        const float4 C = *(const float4*)(rc + c);
        const float4 U = *(const float4*)(smid + r * WW + c);
        const float4 N = *(const float4*)(smid + (r + 2) * WW + c);
        const float le = rc[(c + WW - 1) & (WW - 1)];
        const float ri = rc[(c + 4) & (WW - 1)];
        float4 o;
        o.x = fmaf(D1, U.x + N.x + le  + C.y - 4.0f * C.x, fmaf(r1 * C.x, 1.0f - C.x, C.x));
        o.y = fmaf(D1, U.y + N.y + C.x + C.z - 4.0f * C.y, fmaf(r1 * C.y, 1.0f - C.y, C.y));
        o.z = fmaf(D1, U.z + N.z + C.y + C.w - 4.0f * C.z, fmaf(r1 * C.z, 1.0f - C.z, C.z));
        o.w = fmaf(D1, U.w + N.w + C.z + ri  - 4.0f * C.w, fmaf(r1 * C.w, 1.0f - C.w, C.w));
        *(float4*)(v + ((y0 + r) << 9) + c) = o;
        acc  += (o.x + o.y) + (o.z + o.w);
        acc2 += (o.x * o.x + o.y * o.y) + (o.z * o.z + o.w * o.w);
    }

    // ---- Block reduction of sum & sumsq, one atomic pair per block ----
    const int lane = tid & 31;
    const int wid  = tid >> 5;
    #pragma unroll
    for (int o = 16; o > 0; o >>= 1) {
        acc  += __shfl_down_sync(0xffffffffu, acc,  o);
        acc2 += __shfl_down_sync(0xffffffffu, acc2, o);
    }
    __shared__ float ws[16], ws2[16];
    if (lane == 0) { ws[wid] = acc; ws2[wid] = acc2; }
    __syncthreads();
    if (wid == 0) {
        acc  = (lane < 16) ? ws[lane]  : 0.0f;
        acc2 = (lane < 16) ? ws2[lane] : 0.0f;
        #pragma unroll
        for (int o = 8; o > 0; o >>= 1) {
            acc  += __shfl_down_sync(0x0000ffffu, acc,  o);
            acc2 += __shfl_down_sync(0x0000ffffu, acc2, o);
        }
        if (lane == 0) {
            atomicAdd(&g_sum0[(slot + 1) * BATCH + b],  acc);
            atomicAdd(&g_sumsq[(slot + 1) * BATCH + b], acc2);
        }
    }
}

extern "C" void kernel_launch(void* const* d_in, const int* in_sizes, int n_in,
                              void* d_out, int out_size) {
    const float* x  = (const float*)d_in[0];   // (32,4,512,512)
    const float* Wm = (const float*)d_in[1];   // (4,2)
    const float* bb = (const float*)d_in[2];   // (2,)
    const int*   t  = (const int*)d_in[3];     // (32,)
    float* out = (float*)d_out;

    cudaFuncSetAttribute(fused2_kernel,
                         cudaFuncAttributeMaxDynamicSharedMemorySize, SMEMF);

    zero_sums_kernel<<<1, 256>>>();

    // Copy ch1..3, reduce per-(b,c) sums (+ sumsq for ch0).
    init_kernel<<<dim3(PLANE / 4 / 256, BATCH * NCH), dim3(256)>>>(x, out);

    float* bufA; float* bufB;
    cudaGetSymbolAddress((void**)&bufA, g_buf0);
    cudaGetSymbolAddress((void**)&bufB, g_buf1);

    const dim3 fgrid(HH / TILE, BATCH);   // (32, 32) = 1024 blocks
    // 4 fused kernels: steps (0,1), (2,3), (4,5), (6,7)
    for (int k = 0; k < 4; k++) {
        const int s = 2 * k;
        const float* src;  int sstride;
        float*       dst;  int dstride;
        if (k == 0) { src = x;  sstride = NCH * PLANE; }
        else        { src = (k & 1) ? bufA : bufB; sstride = PLANE; }
        if (k == 3) { dst = out; dstride = NCH * PLANE; }
        else        { dst = (k & 1) ? bufB : bufA; dstride = PLANE; }
        fused2_kernel<<<fgrid, THREADS_F, SMEMF>>>(src, sstride, dst, dstride,
                                                   Wm, bb, t, s);
    }
}

// round 9
// speedup vs baseline: 1.1400x; 1.1400x over previous
#include <cuda_runtime.h>

#define BATCH 32
#define NCH   4
#define HH    512
#define WW    512
#define PLANE (HH*WW)          /* 262144 */
#define NSTEPS 8
#define D_SCALE 0.2f
#define RHO_SCALE 0.1f

#define TILE   16               /* output rows per block */
#define MIDR   (TILE + 2)       /* 18 intermediate rows kept in smem */
#define THREADS_F 256           /* 8 warps: 4 chunks x 2 row-groups */
#define SMEMF  (MIDR * WW * 4)  /* 36864 bytes */

// Ping-pong scratch for the evolving channel-0 field (2 x 32 MiB).
__device__ float g_buf0[BATCH * PLANE];
__device__ float g_buf1[BATCH * PLANE];
// Sums at even steps 0,2,4,6,8: slot k = state entering fused kernel k.
__device__ float g_sum0[5 * BATCH];
__device__ float g_sumsq[5 * BATCH];
// Constant sums of channels 1..3 (index (c-1)*BATCH + b).
__device__ float g_sumc[3 * BATCH];

__global__ void zero_sums_kernel() {
    int i = threadIdx.x;
    if (i < 5 * BATCH) { g_sum0[i] = 0.0f; g_sumsq[i] = 0.0f; }
    if (i < 3 * BATCH) g_sumc[i] = 0.0f;
}

// Copy channels 1..3 input->output; reduce sums (and sumsq for ch0).
// grid = (PLANE/4/256, BATCH*NCH), block = 256.
__global__ void init_kernel(const float* __restrict__ x, float* __restrict__ out) {
    const int p = blockIdx.y;            // plane id = b*4 + c
    const int b = p >> 2;
    const int c = p & 3;
    const int i = blockIdx.x * blockDim.x + threadIdx.x;

    const float4* src = (const float4*)(x + (size_t)p * PLANE);
    float4 v = src[i];
    if (c != 0) {
        ((float4*)(out + (size_t)p * PLANE))[i] = v;
    }
    float s  = (v.x + v.y) + (v.z + v.w);
    float s2 = (v.x * v.x + v.y * v.y) + (v.z * v.z + v.w * v.w);

    #pragma unroll
    for (int o = 16; o > 0; o >>= 1) {
        s  += __shfl_down_sync(0xffffffffu, s,  o);
        s2 += __shfl_down_sync(0xffffffffu, s2, o);
    }
    __shared__ float ws[8], ws2[8];
    const int lane = threadIdx.x & 31;
    const int w    = threadIdx.x >> 5;
    if (lane == 0) { ws[w] = s; ws2[w] = s2; }
    __syncthreads();
    if (w == 0) {
        s  = (lane < 8) ? ws[lane]  : 0.0f;
        s2 = (lane < 8) ? ws2[lane] : 0.0f;
        #pragma unroll
        for (int o = 4; o > 0; o >>= 1) {
            s  += __shfl_down_sync(0x000000ffu, s,  o);
            s2 += __shfl_down_sync(0x000000ffu, s2, o);
        }
        if (lane == 0) {
            if (c == 0) {
                atomicAdd(&g_sum0[b],  s);
                atomicAdd(&g_sumsq[b], s2);
            } else {
                atomicAdd(&g_sumc[(c - 1) * BATCH + b], s);
            }
        }
    }
}

// TWO fused reaction-diffusion steps (s, s+1) on channel 0.
//   sum_{s+1} = sum_s + rho_s * (sum_s - sumsq_s)   (periodic BC: sum(lap)=0)
// Stage B: warp = (chunk, 9-row group); 11 input rows gmem->registers
//   (MLP=11), shfl horizontals, edge scalars prefetched -> 9 intermediate
//   rows stored to smem (only smem write).
// Stage C: warp = (chunk, 8-row group); rolls 3 smem rows (1 LDS.128/iter),
//   shfl horizontals, edge scalars from smem -> gmem + sum/sumsq reduce.
// grid = (HH/TILE, BATCH) = (32, 32), block = 256, dyn smem = SMEMF.
__global__ __launch_bounds__(THREADS_F) void fused2_kernel(
        const float* __restrict__ src, int src_bstride,
        float* __restrict__ dst, int dst_bstride,
        const float* __restrict__ Wm,
        const float* __restrict__ bias,
        const int* __restrict__ t, int s) {
    extern __shared__ float smid[];   // MIDR rows x 512; row k = intermediate rel (k-1)

    const int b    = blockIdx.y;
    const int y0   = blockIdx.x * TILE;
    const int tid  = threadIdx.x;
    const int lane = tid & 31;
    const int wid  = tid >> 5;
    const int chunk = wid & 3;
    const int grp   = wid >> 2;                 // 0 or 1

    const float* __restrict__ u = src + (size_t)b * src_bstride;
    float* __restrict__ v       = dst + (size_t)b * dst_bstride;

    const int xb = chunk << 7;
    const int x4 = xb + (lane << 2);
    const int xl = (xb + WW - 1) & (WW - 1);
    const int xr = (xb + 128) & (WW - 1);

    // ---- Stage B input: 11 rows gmem->regs, MLP=11 ----
    // Intermediate rel rows for this warp: im = -1 + 9*grp + i, i=0..8
    // Input rows global: y0 - 2 + 9*grp + k, k=0..10 (wrapped)
    const int inbase = y0 - 2 + 9 * grp;
    float4 R[11];
    #pragma unroll
    for (int k = 0; k < 11; k++)
        R[k] = *(const float4*)(u + (((inbase + k) & (HH - 1)) << 9) + x4);

    // edge scalars of input rows y0-1+9*grp+i (i=0..8): lanes 0-8 left, 16-24 right
    float edgeB = 0.0f;
    if (lane < 9)
        edgeB = u[(((inbase + 1 + lane) & (HH - 1)) << 9) + xl];
    else if (lane >= 16 && lane < 25)
        edgeB = u[(((inbase + 1 + (lane - 16)) & (HH - 1)) << 9) + xr];

    // ---- D/rho for both sub-steps (overlaps loads) ----
    const int slot = s >> 1;
    const float inv = 1.0f / (float)PLANE;
    const float sum_s = g_sum0[slot * BATCH + b];
    const float ssq_s = g_sumsq[slot * BATCH + b];
    const float f1 = g_sumc[0 * BATCH + b] * inv;
    const float f2 = g_sumc[1 * BATCH + b] * inv;
    const float f3 = g_sumc[2 * BATCH + b] * inv;
    const float zc0 = f1 * Wm[2] + f2 * Wm[4] + f3 * Wm[6] + bias[0];
    const float zc1 = f1 * Wm[3] + f2 * Wm[5] + f3 * Wm[7] + bias[1];
    const int tb = t[b];

    const float f0 = sum_s * inv;
    float D0 = D_SCALE   / (1.0f + expf(-(f0 * Wm[0] + zc0)));
    float r0 = RHO_SCALE / (1.0f + expf(-(f0 * Wm[1] + zc1)));
    if (tb <= s) { D0 = 0.0f; r0 = 0.0f; }

    const float sum_n = sum_s + r0 * (sum_s - ssq_s);   // exact under periodic BC
    const float f0n = sum_n * inv;
    float D1 = D_SCALE   / (1.0f + expf(-(f0n * Wm[0] + zc0)));
    float r1 = RHO_SCALE / (1.0f + expf(-(f0n * Wm[1] + zc1)));
    if (tb <= s + 1) { D1 = 0.0f; r1 = 0.0f; }

    // ---- Stage B: 9 intermediate rows -> smem ----
    #pragma unroll
    for (int i = 0; i < 9; i++) {
        const float4 P = R[i], C = R[i + 1], N = R[i + 2];
        const float leB = __shfl_sync(0xffffffffu, edgeB, i);
        const float riB = __shfl_sync(0xffffffffu, edgeB, 16 + i);
        float le = __shfl_up_sync(0xffffffffu, C.w, 1);
        float ri = __shfl_down_sync(0xffffffffu, C.x, 1);
        if (lane == 0)  le = leB;
        if (lane == 31) ri = riB;

        float4 o;
        o.x = fmaf(D0, P.x + N.x + le  + C.y - 4.0f * C.x, fmaf(r0 * C.x, 1.0f - C.x, C.x));
        o.y = fmaf(D0, P.y + N.y + C.x + C.z - 4.0f * C.y, fmaf(r0 * C.y, 1.0f - C.y, C.y));
        o.z = fmaf(D0, P.z + N.z + C.y + C.w - 4.0f * C.z, fmaf(r0 * C.z, 1.0f - C.z, C.z));
        o.w = fmaf(D0, P.w + N.w + C.z + ri  - 4.0f * C.w, fmaf(r0 * C.w, 1.0f - C.w, C.w));
        *(float4*)(smid + (9 * grp + i) * WW + x4) = o;   // smem row = im+1
    }
    __syncthreads();

    // ---- Stage C: 8 output rows per warp from smem ----
    // out rel row j = 8*grp + i (i=0..7); needs smem rows j, j+1, j+2.
    const int j0 = 8 * grp;

    // intermediate edge scalars at rel row j (smem row j+1): lanes 0-7 left, 16-23 right
    float edgeC = 0.0f;
    if (lane < 8)
        edgeC = smid[(j0 + lane + 1) * WW + xl];
    else if (lane >= 16 && lane < 24)
        edgeC = smid[(j0 + (lane - 16) + 1) * WW + xr];

    float4 P = *(const float4*)(smid + j0 * WW + x4);
    float4 C = *(const float4*)(smid + (j0 + 1) * WW + x4);

    float acc = 0.0f, acc2 = 0.0f;
    #pragma unroll
    for (int i = 0; i < 8; i++) {
        const float4 N = *(const float4*)(smid + (j0 + i + 2) * WW + x4);

        const float leB = __shfl_sync(0xffffffffu, edgeC, i);
        const float riB = __shfl_sync(0xffffffffu, edgeC, 16 + i);
        float le = __shfl_up_sync(0xffffffffu, C.w, 1);
        float ri = __shfl_down_sync(0xffffffffu, C.x, 1);
        if (lane == 0)  le = leB;
        if (lane == 31) ri = riB;

        float4 o;
        o.x = fmaf(D1, P.x + N.x + le  + C.y - 4.0f * C.x, fmaf(r1 * C.x, 1.0f - C.x, C.x));
        o.y = fmaf(D1, P.y + N.y + C.x + C.z - 4.0f * C.y, fmaf(r1 * C.y, 1.0f - C.y, C.y));
        o.z = fmaf(D1, P.z + N.z + C.y + C.w - 4.0f * C.z, fmaf(r1 * C.z, 1.0f - C.z, C.z));
        o.w = fmaf(D1, P.w + N.w + C.z + ri  - 4.0f * C.w, fmaf(r1 * C.w, 1.0f - C.w, C.w));

        *(float4*)(v + ((y0 + j0 + i) << 9) + x4) = o;
        acc  += (o.x + o.y) + (o.z + o.w);
        acc2 += (o.x * o.x + o.y * o.y) + (o.z * o.z + o.w * o.w);

        P = C; C = N;
    }

    // ---- Block reduction of sum & sumsq, one atomic pair per block ----
    #pragma unroll
    for (int o = 16; o > 0; o >>= 1) {
        acc  += __shfl_down_sync(0xffffffffu, acc,  o);
        acc2 += __shfl_down_sync(0xffffffffu, acc2, o);
    }
    __shared__ float ws[8], ws2[8];
    if (lane == 0) { ws[wid] = acc; ws2[wid] = acc2; }
    __syncthreads();
    if (wid == 0) {
        acc  = (lane < 8) ? ws[lane]  : 0.0f;
        acc2 = (lane < 8) ? ws2[lane] : 0.0f;
        #pragma unroll
        for (int o = 4; o > 0; o >>= 1) {
            acc  += __shfl_down_sync(0x000000ffu, acc,  o);
            acc2 += __shfl_down_sync(0x000000ffu, acc2, o);
        }
        if (lane == 0) {
            atomicAdd(&g_sum0[(slot + 1) * BATCH + b],  acc);
            atomicAdd(&g_sumsq[(slot + 1) * BATCH + b], acc2);
        }
    }
}

extern "C" void kernel_launch(void* const* d_in, const int* in_sizes, int n_in,
                              void* d_out, int out_size) {
    const float* x  = (const float*)d_in[0];   // (32,4,512,512)
    const float* Wm = (const float*)d_in[1];   // (4,2)
    const float* bb = (const float*)d_in[2];   // (2,)
    const int*   t  = (const int*)d_in[3];     // (32,)
    float* out = (float*)d_out;

    cudaFuncSetAttribute(fused2_kernel,
                         cudaFuncAttributeMaxDynamicSharedMemorySize, SMEMF);

    zero_sums_kernel<<<1, 256>>>();

    // Copy ch1..3, reduce per-(b,c) sums (+ sumsq for ch0).
    init_kernel<<<dim3(PLANE / 4 / 256, BATCH * NCH), dim3(256)>>>(x, out);

    float* bufA; float* bufB;
    cudaGetSymbolAddress((void**)&bufA, g_buf0);
    cudaGetSymbolAddress((void**)&bufB, g_buf1);

    const dim3 fgrid(HH / TILE, BATCH);   // (32, 32) = 1024 blocks
    // 4 fused kernels: steps (0,1), (2,3), (4,5), (6,7)
    for (int k = 0; k < 4; k++) {
        const int s = 2 * k;
        const float* src;  int sstride;
        float*       dst;  int dstride;
        if (k == 0) { src = x;  sstride = NCH * PLANE; }
        else        { src = (k & 1) ? bufA : bufB; sstride = PLANE; }
        if (k == 3) { dst = out; dstride = NCH * PLANE; }
        else        { dst = (k & 1) ? bufB : bufA; dstride = PLANE; }
        fused2_kernel<<<fgrid, THREADS_F, SMEMF>>>(src, sstride, dst, dstride,
                                                   Wm, bb, t, s);
    }
}

// round 10
// speedup vs baseline: 1.3173x; 1.1555x over previous
#include <cuda_runtime.h>

#define BATCH 32
#define NCH   4
#define HH    512
#define WW    512
#define PLANE (HH*WW)          /* 262144 */
#define NSTEPS 8
#define D_SCALE 0.2f
#define RHO_SCALE 0.1f
#define FULLM 0xffffffffu

// Ping-pong scratch for the evolving channel-0 field (2 x 32 MiB).
__device__ float g_buf0[BATCH * PLANE];
__device__ float g_buf1[BATCH * PLANE];
// Sums at even steps 0,2,4,6,8: slot k = state entering fused kernel k.
__device__ float g_sum0[5 * BATCH];
__device__ float g_sumsq[5 * BATCH];
// Constant sums of channels 1..3 (index (c-1)*BATCH + b).
__device__ float g_sumc[3 * BATCH];

__global__ void zero_sums_kernel() {
    int i = threadIdx.x;
    if (i < 5 * BATCH) { g_sum0[i] = 0.0f; g_sumsq[i] = 0.0f; }
    if (i < 3 * BATCH) g_sumc[i] = 0.0f;
}

// Copy channels 1..3 input->output; reduce sums (and sumsq for ch0).
__global__ void init_kernel(const float* __restrict__ x, float* __restrict__ out) {
    const int p = blockIdx.y;            // plane id = b*4 + c
    const int b = p >> 2;
    const int c = p & 3;
    const int i = blockIdx.x * blockDim.x + threadIdx.x;

    const float4* src = (const float4*)(x + (size_t)p * PLANE);
    float4 v = src[i];
    if (c != 0) {
        ((float4*)(out + (size_t)p * PLANE))[i] = v;
    }
    float s  = (v.x + v.y) + (v.z + v.w);
    float s2 = (v.x * v.x + v.y * v.y) + (v.z * v.z + v.w * v.w);

    #pragma unroll
    for (int o = 16; o > 0; o >>= 1) {
        s  += __shfl_down_sync(FULLM, s,  o);
        s2 += __shfl_down_sync(FULLM, s2, o);
    }
    __shared__ float ws[8], ws2[8];
    const int lane = threadIdx.x & 31;
    const int w    = threadIdx.x >> 5;
    if (lane == 0) { ws[w] = s; ws2[w] = s2; }
    __syncthreads();
    if (w == 0) {
        s  = (lane < 8) ? ws[lane]  : 0.0f;
        s2 = (lane < 8) ? ws2[lane] : 0.0f;
        #pragma unroll
        for (int o = 4; o > 0; o >>= 1) {
            s  += __shfl_down_sync(0x000000ffu, s,  o);
            s2 += __shfl_down_sync(0x000000ffu, s2, o);
        }
        if (lane == 0) {
            if (c == 0) {
                atomicAdd(&g_sum0[b],  s);
                atomicAdd(&g_sumsq[b], s2);
            } else {
                atomicAdd(&g_sumc[(c - 1) * BATCH + b], s);
            }
        }
    }
}

// TWO fused reaction-diffusion steps, warp-private (no smem, no syncthreads).
//   sum_{s+1} = sum_s + rho_s*(sum_s - sumsq_s)   (periodic: sum(lap)=0)
// Warp = (chunk of 128 cols, strip of 8 output rows). Loads 12 input rows
// (MLP=12) + 4 small edge loads (lanes 0..11). Computes the 10 intermediate
// rows it needs (incl. the 2-col redundant edge intermediates in-lane),
// rolls them in 3 float4 registers, writes 8 output rows + sum/sumsq.
// grid = (HH/16, BATCH) = (32, 32), block = 256 (8 warps: 4 chunks x 2 grps).
__global__ __launch_bounds__(256) void fused2_kernel(
        const float* __restrict__ src, int src_bstride,
        float* __restrict__ dst, int dst_bstride,
        const float* __restrict__ Wm,
        const float* __restrict__ bias,
        const int* __restrict__ t, int s) {
    const int b    = blockIdx.y;
    const int tid  = threadIdx.x;
    const int lane = tid & 31;
    const int wid  = tid >> 5;
    const int chunk = wid & 3;
    const int grp   = wid >> 2;                 // 0 or 1
    const int y0    = blockIdx.x * 16 + grp * 8;

    const float* __restrict__ u = src + (size_t)b * src_bstride;
    float* __restrict__ v       = dst + (size_t)b * dst_bstride;

    const int xb  = chunk << 7;
    const int x4  = xb + (lane << 2);
    const int xl2 = (xb + WW - 2) & (WW - 1);   // cols xb-2, xb-1 (float2)
    const int xr2 = (xb + 128) & (WW - 1);      // cols xb+128, xb+129 (float2)

    // ---- Batch loads: 12 main rows (MLP=12) + edge data (lanes 0..11) ----
    float4 R[12];
    #pragma unroll
    for (int k = 0; k < 12; k++)
        R[k] = *(const float4*)(u + (((y0 - 2 + k) & (HH - 1)) << 9) + x4);

    float2 eL = make_float2(0.f, 0.f), eR = make_float2(0.f, 0.f);
    float sxb = 0.0f, sxbr = 0.0f;
    if (lane < 12) {
        const int row = ((y0 - 2 + lane) & (HH - 1)) << 9;
        eL   = *(const float2*)(u + row + xl2);   // (xb-2, xb-1)
        eR   = *(const float2*)(u + row + xr2);   // (xb+128, xb+129)
        sxb  = u[row + xb];                       // col xb
        sxbr = u[row + xb + 127];                 // col xb+127
    }

    // ---- D/rho for both sub-steps (overlaps loads) ----
    const int slot = s >> 1;
    const float inv = 1.0f / (float)PLANE;
    const float sum_s = g_sum0[slot * BATCH + b];
    const float ssq_s = g_sumsq[slot * BATCH + b];
    const float f1 = g_sumc[0 * BATCH + b] * inv;
    const float f2 = g_sumc[1 * BATCH + b] * inv;
    const float f3 = g_sumc[2 * BATCH + b] * inv;
    const float zc0 = f1 * Wm[2] + f2 * Wm[4] + f3 * Wm[6] + bias[0];
    const float zc1 = f1 * Wm[3] + f2 * Wm[5] + f3 * Wm[7] + bias[1];
    const int tb = t[b];

    const float f0 = sum_s * inv;
    float D0 = D_SCALE   / (1.0f + __expf(-(f0 * Wm[0] + zc0)));
    float r0 = RHO_SCALE / (1.0f + __expf(-(f0 * Wm[1] + zc1)));
    if (tb <= s) { D0 = 0.0f; r0 = 0.0f; }

    const float sum_n = sum_s + r0 * (sum_s - ssq_s);   // exact (periodic BC)
    const float f0n = sum_n * inv;
    float D1 = D_SCALE   / (1.0f + __expf(-(f0n * Wm[0] + zc0)));
    float r1 = RHO_SCALE / (1.0f + __expf(-(f0n * Wm[1] + zc1)));
    if (tb <= s + 1) { D1 = 0.0f; r1 = 0.0f; }

    // ---- Edge intermediates: lane i = row y0-2+i (valid i=1..10) ----
    float iLv, iRv;
    {
        float up = __shfl_up_sync(FULLM, eL.y, 1);
        float dn = __shfl_down_sync(FULLM, eL.y, 1);
        iLv = fmaf(D0, up + dn + eL.x + sxb - 4.0f * eL.y,
                   fmaf(r0 * eL.y, 1.0f - eL.y, eL.y));
        up = __shfl_up_sync(FULLM, eR.x, 1);
        dn = __shfl_down_sync(FULLM, eR.x, 1);
        iRv = fmaf(D0, up + dn + sxbr + eR.y - 4.0f * eR.x,
                   fmaf(r0 * eR.x, 1.0f - eR.x, eR.x));
    }

    // ---- Main loop: intermediates m=0..9 (rows y0-1..y0+8), outputs j=m-2 ----
    float4 I[3];
    float acc = 0.0f, acc2 = 0.0f;
    #pragma unroll
    for (int m = 0; m < 10; m++) {
        const float4 P = R[m], C = R[m + 1], N = R[m + 2];
        const float lein = __shfl_sync(FULLM, eL.y, m + 1);
        const float riin = __shfl_sync(FULLM, eR.x, m + 1);
        float le = __shfl_up_sync(FULLM, C.w, 1);
        float ri = __shfl_down_sync(FULLM, C.x, 1);
        if (lane == 0)  le = lein;
        if (lane == 31) ri = riin;

        float4 o;
        o.x = fmaf(D0, P.x + N.x + le  + C.y - 4.0f * C.x, fmaf(r0 * C.x, 1.0f - C.x, C.x));
        o.y = fmaf(D0, P.y + N.y + C.x + C.z - 4.0f * C.y, fmaf(r0 * C.y, 1.0f - C.y, C.y));
        o.z = fmaf(D0, P.z + N.z + C.y + C.w - 4.0f * C.z, fmaf(r0 * C.z, 1.0f - C.z, C.z));
        o.w = fmaf(D0, P.w + N.w + C.z + ri  - 4.0f * C.w, fmaf(r0 * C.w, 1.0f - C.w, C.w));
        I[m % 3] = o;

        if (m >= 2) {
            const int j = m - 2;                      // output row y0+j
            const float4 Pm = I[j % 3];               // row y0+j-1
            const float4 Cm = I[(j + 1) % 3];         // row y0+j
            const float4 Nm = I[(j + 2) % 3];         // row y0+j+1
            const float leo = __shfl_sync(FULLM, iLv, j + 2);
            const float rio = __shfl_sync(FULLM, iRv, j + 2);
            float le2 = __shfl_up_sync(FULLM, Cm.w, 1);
            float ri2 = __shfl_down_sync(FULLM, Cm.x, 1);
            if (lane == 0)  le2 = leo;
            if (lane == 31) ri2 = rio;

            float4 q;
            q.x = fmaf(D1, Pm.x + Nm.x + le2 + Cm.y - 4.0f * Cm.x, fmaf(r1 * Cm.x, 1.0f - Cm.x, Cm.x));
            q.y = fmaf(D1, Pm.y + Nm.y + Cm.x + Cm.z - 4.0f * Cm.y, fmaf(r1 * Cm.y, 1.0f - Cm.y, Cm.y));
            q.z = fmaf(D1, Pm.z + Nm.z + Cm.y + Cm.w - 4.0f * Cm.z, fmaf(r1 * Cm.z, 1.0f - Cm.z, Cm.z));
            q.w = fmaf(D1, Pm.w + Nm.w + Cm.z + ri2  - 4.0f * Cm.w, fmaf(r1 * Cm.w, 1.0f - Cm.w, Cm.w));

            *(float4*)(v + ((y0 + j) << 9) + x4) = q;
            acc  += (q.x + q.y) + (q.z + q.w);
            acc2 += (q.x * q.x + q.y * q.y) + (q.z * q.z + q.w * q.w);
        }
    }

    // ---- Block reduction of sum & sumsq, one atomic pair per block ----
    #pragma unroll
    for (int o = 16; o > 0; o >>= 1) {
        acc  += __shfl_down_sync(FULLM, acc,  o);
        acc2 += __shfl_down_sync(FULLM, acc2, o);
    }
    __shared__ float ws[8], ws2[8];
    if (lane == 0) { ws[wid] = acc; ws2[wid] = acc2; }
    __syncthreads();
    if (wid == 0) {
        acc  = (lane < 8) ? ws[lane]  : 0.0f;
        acc2 = (lane < 8) ? ws2[lane] : 0.0f;
        #pragma unroll
        for (int o = 4; o > 0; o >>= 1) {
            acc  += __shfl_down_sync(0x000000ffu, acc,  o);
            acc2 += __shfl_down_sync(0x000000ffu, acc2, o);
        }
        if (lane == 0) {
            atomicAdd(&g_sum0[(slot + 1) * BATCH + b],  acc);
            atomicAdd(&g_sumsq[(slot + 1) * BATCH + b], acc2);
        }
    }
}

extern "C" void kernel_launch(void* const* d_in, const int* in_sizes, int n_in,
                              void* d_out, int out_size) {
    const float* x  = (const float*)d_in[0];   // (32,4,512,512)
    const float* Wm = (const float*)d_in[1];   // (4,2)
    const float* bb = (const float*)d_in[2];   // (2,)
    const int*   t  = (const int*)d_in[3];     // (32,)
    float* out = (float*)d_out;

    zero_sums_kernel<<<1, 256>>>();

    // Copy ch1..3, reduce per-(b,c) sums (+ sumsq for ch0).
    init_kernel<<<dim3(PLANE / 4 / 256, BATCH * NCH), dim3(256)>>>(x, out);

    float* bufA; float* bufB;
    cudaGetSymbolAddress((void**)&bufA, g_buf0);
    cudaGetSymbolAddress((void**)&bufB, g_buf1);

    const dim3 fgrid(HH / 16, BATCH);   // (32, 32) = 1024 blocks
    // 4 fused kernels: steps (0,1), (2,3), (4,5), (6,7)
    for (int k = 0; k < 4; k++) {
        const int s = 2 * k;
        const float* src;  int sstride;
        float*       dst;  int dstride;
        if (k == 0) { src = x;  sstride = NCH * PLANE; }
        else        { src = (k & 1) ? bufA : bufB; sstride = PLANE; }
        if (k == 3) { dst = out; dstride = NCH * PLANE; }
        else        { dst = (k & 1) ? bufB : bufA; dstride = PLANE; }
        fused2_kernel<<<fgrid, 256>>>(src, sstride, dst, dstride, Wm, bb, t, s);
    }
}